// round 7
// baseline (speedup 1.0000x reference)
#include <cuda_runtime.h>
#include <cuda_fp16.h>
#include <math.h>
#include <stdint.h>

#define BATCH 4
#define SEQ   4096
#define DIM   512
#define MTOT  (BATCH * SEQ)
#define NTILE (SEQ / 128)
#define NEG_INF __int_as_float(0xff800000)

// ---------------- scratch (static device globals; no allocation) ------------
__device__ __half g_Xh[(size_t)MTOT * DIM],  g_Xl[(size_t)MTOT * DIM];
__device__ __half g_Wh[3][DIM * DIM],        g_Wl[3][DIM * DIM];
__device__ __half g_Qh[(size_t)MTOT * DIM],  g_Ql[(size_t)MTOT * DIM];
__device__ __half g_Kh[(size_t)MTOT * DIM],  g_Kl[(size_t)MTOT * DIM];
__device__ __half g_Vth[(size_t)DIM * MTOT];                 // V^T, hi plane only
__device__ float  g_S [(size_t)BATCH * SEQ * SEQ];
__device__ float  g_cm[(size_t)NTILE * BATCH * SEQ];         // per-qtile col max
__device__ float  g_cz[(size_t)NTILE * BATCH * SEQ];         // per-qtile col sumexp
__device__ float  g_c [(size_t)BATCH * SEQ];                 // m_k + ln(Z_k)

// ---------------- fast exp on the FMA pipe (no MUFU) -------------------------
__device__ __forceinline__ float fast_exp(float x) {
    x = fmaxf(x, -80.0f);
    const float y  = x * 1.4426950408889634f;
    const float t  = y + 12582912.0f;                    // 1.5*2^23 magic round
    const int   ni = __float_as_int(t) - 0x4B400000;
    const float f  = y - (t - 12582912.0f);
    float p = 1.3333558146e-3f;
    p = fmaf(p, f, 9.6181291076e-3f);
    p = fmaf(p, f, 5.5504108664e-2f);
    p = fmaf(p, f, 2.4022650696e-1f);
    p = fmaf(p, f, 6.9314718056e-1f);
    p = fmaf(p, f, 1.0f);
    return __int_as_float(__float_as_int(p) + (ni << 23));
}

// ============================ PTX helpers ===================================
__device__ __forceinline__ uint32_t smem_u32(const void* p) {
    uint32_t a;
    asm("{ .reg .u64 t; cvta.to.shared.u64 t, %1; cvt.u32.u64 %0, t; }"
        : "=r"(a) : "l"(p));
    return a;
}
template<int N> __device__ __forceinline__ void cp_wait() {
    asm volatile("cp.async.wait_group %0;" :: "n"(N) : "memory");
}
__device__ __forceinline__ void cp_commit() {
    asm volatile("cp.async.commit_group;" ::: "memory");
}
__device__ __forceinline__ void cp16(uint32_t dst, const void* src) {
    asm volatile("cp.async.cg.shared.global [%0], [%1], 16;"
                 :: "r"(dst), "l"(src) : "memory");
}
__device__ __forceinline__ void ldsm4(uint32_t* r, uint32_t a) {
    asm volatile("ldmatrix.sync.aligned.m8n8.x4.shared.b16 {%0,%1,%2,%3}, [%4];"
                 : "=r"(r[0]), "=r"(r[1]), "=r"(r[2]), "=r"(r[3]) : "r"(a));
}
__device__ __forceinline__ void mma16816(float* d, const uint32_t* a,
                                         uint32_t b0, uint32_t b1) {
    asm volatile("mma.sync.aligned.m16n8k16.row.col.f32.f16.f16.f32 "
                 "{%0,%1,%2,%3},{%4,%5,%6,%7},{%8,%9},{%0,%1,%2,%3};"
                 : "+f"(d[0]), "+f"(d[1]), "+f"(d[2]), "+f"(d[3])
                 : "r"(a[0]), "r"(a[1]), "r"(a[2]), "r"(a[3]), "r"(b0), "r"(b1));
}

// ============================ GEMM (hi/lo fp16) ==============================
// C[m,n] = sum_k A[m,k]*B[n,k]   (3 MMAs: AhBh + AlBh + AhBl)
// EPI 1: fp16 hi/lo planes Ch/Cl[m][n] (+bias)
// EPI 2: fp16 hi plane Ch[n][m] (+bias)  -- transposed (for V^T)
// EPI 3: fp32 C[m][n] + per-tile column softmax stats -> g_cm/g_cz
#define TCT 256

template<int EPI>
__global__ void __launch_bounds__(TCT, 2)
gemm_hl(const __half* __restrict__ Ah, const __half* __restrict__ Al,
        const __half* __restrict__ Bh, const __half* __restrict__ Bl,
        const float* __restrict__ bias,
        float* __restrict__ C, __half* __restrict__ Ch, __half* __restrict__ Cl,
        int K, int lda, int ldb, int ldc,
        long sA, long sB, long sC)
{
    constexpr int OFF_AL = 8192;
    constexpr int OFF_BH = 16384;
    constexpr int OFF_BL = 24576;
    constexpr int STG    = 32768;

    extern __shared__ __align__(128) char smem[];
    const uint32_t sb = smem_u32(smem);

    const int tid = threadIdx.x;
    const int lid = tid & 31;
    const int wid = tid >> 5;
    const int wm  = wid >> 2;
    const int wn  = wid & 3;

    const long z = blockIdx.z;
    Ah += z * sA; Al += z * sA;
    Bh += z * sB; Bl += z * sB;
    if (EPI == 3) C += z * sC; else { Ch += z * sC; if (EPI == 1) Cl += z * sC; }

    const int m0 = blockIdx.y * 128;
    const int n0 = blockIdx.x * 128;

    const int nstage = K / 32;

    auto issue = [&](int s) {
        const uint32_t base = sb + (s & 1) * STG;
        const int k0 = s * 32;
#pragma unroll
        for (int i = 0; i < 2; i++) {
            const int chunk = i * 256 + tid;
            const int r = chunk >> 2;
            const int c = chunk & 3;
            const uint32_t doff = r * 64 + ((c ^ ((r + (r >> 2)) & 3)) * 16);
            const size_t ga = (size_t)(m0 + r) * lda + k0 + c * 8;
            const size_t gb = (size_t)(n0 + r) * ldb + k0 + c * 8;
            cp16(base + doff, Ah + ga);
            cp16(base + OFF_AL + doff, Al + ga);
            cp16(base + OFF_BH + doff, Bh + gb);
            cp16(base + OFF_BL + doff, Bl + gb);
        }
        cp_commit();
    };

    float acc[4][4][4];
#pragma unroll
    for (int a = 0; a < 4; a++)
#pragma unroll
        for (int b = 0; b < 4; b++)
#pragma unroll
            for (int c = 0; c < 4; c++) acc[a][b][c] = 0.f;

    const int sub   = lid >> 3;
    const int lane7 = lid & 7;
    const int rA = wm * 64 + (sub & 1) * 8 + lane7;
    const int rB = wn * 32 + (sub & 1) * 8 + lane7;
    const int cs = sub >> 1;
    const int swA = (rA + (rA >> 2)) & 3;
    const int swB = (rB + (rB >> 2)) & 3;

    issue(0);
    issue(1);

    for (int s = 0; s < nstage; s++) {
        if (s + 1 < nstage) cp_wait<1>(); else cp_wait<0>();
        __syncthreads();

        const uint32_t stg = sb + (s & 1) * STG;
#pragma unroll
        for (int kt = 0; kt < 2; kt++) {
            const int ch = 2 * kt + cs;
            const uint32_t aoff = ((ch ^ swA) * 16);
            const uint32_t boff = ((ch ^ swB) * 16);

            uint32_t aH[4][4], bH[2][4];
#pragma unroll
            for (int mf = 0; mf < 4; mf++)
                ldsm4(aH[mf], stg + (rA + mf * 16) * 64 + aoff);
#pragma unroll
            for (int bg = 0; bg < 2; bg++)
                ldsm4(bH[bg], stg + OFF_BH + (rB + bg * 16) * 64 + boff);

#pragma unroll
            for (int mf = 0; mf < 4; mf++)
#pragma unroll
                for (int nf = 0; nf < 4; nf++)
                    mma16816(acc[mf][nf], aH[mf],
                             bH[nf >> 1][nf & 1], bH[nf >> 1][(nf & 1) + 2]);

            {
                uint32_t aL[4][4];
#pragma unroll
                for (int mf = 0; mf < 4; mf++)
                    ldsm4(aL[mf], stg + OFF_AL + (rA + mf * 16) * 64 + aoff);
#pragma unroll
                for (int mf = 0; mf < 4; mf++)
#pragma unroll
                    for (int nf = 0; nf < 4; nf++)
                        mma16816(acc[mf][nf], aL[mf],
                                 bH[nf >> 1][nf & 1], bH[nf >> 1][(nf & 1) + 2]);
            }
            {
                uint32_t bL[2][4];
#pragma unroll
                for (int bg = 0; bg < 2; bg++)
                    ldsm4(bL[bg], stg + OFF_BL + (rB + bg * 16) * 64 + boff);
#pragma unroll
                for (int mf = 0; mf < 4; mf++)
#pragma unroll
                    for (int nf = 0; nf < 4; nf++)
                        mma16816(acc[mf][nf], aH[mf],
                                 bL[nf >> 1][nf & 1], bL[nf >> 1][(nf & 1) + 2]);
            }
        }

        if (s + 2 < nstage) {
            __syncthreads();
            issue(s + 2);
        }
    }

    // -------------------------- epilogue ------------------------------------
#pragma unroll
    for (int mf = 0; mf < 4; mf++) {
#pragma unroll
        for (int nf = 0; nf < 4; nf++) {
            const int m = m0 + wm * 64 + mf * 16 + (lid >> 2);
            const int n = n0 + wn * 32 + nf * 8 + (lid & 3) * 2;
            float v0 = acc[mf][nf][0], v1 = acc[mf][nf][1];
            float v2 = acc[mf][nf][2], v3 = acc[mf][nf][3];
            if (EPI == 1 || EPI == 2) {
                const float b0 = bias[n], b1 = bias[n + 1];
                v0 += b0; v1 += b1; v2 += b0; v3 += b1;
            }
            if (EPI == 3) {
                *(float2*)(C + (size_t)m * ldc + n)       = make_float2(v0, v1);
                *(float2*)(C + (size_t)(m + 8) * ldc + n) = make_float2(v2, v3);
            } else {
                __half h0 = __float2half_rn(v0), h1 = __float2half_rn(v1);
                __half h2 = __float2half_rn(v2), h3 = __float2half_rn(v3);
                if (EPI == 1) {
                    __half l0 = __float2half_rn(v0 - __half2float(h0));
                    __half l1 = __float2half_rn(v1 - __half2float(h1));
                    __half l2 = __float2half_rn(v2 - __half2float(h2));
                    __half l3 = __float2half_rn(v3 - __half2float(h3));
                    *(__half2*)(Ch + (size_t)m * ldc + n)       = __halves2half2(h0, h1);
                    *(__half2*)(Ch + (size_t)(m + 8) * ldc + n) = __halves2half2(h2, h3);
                    *(__half2*)(Cl + (size_t)m * ldc + n)       = __halves2half2(l0, l1);
                    *(__half2*)(Cl + (size_t)(m + 8) * ldc + n) = __halves2half2(l2, l3);
                } else {
                    Ch[(size_t)n * ldc + m]           = h0;
                    Ch[(size_t)(n + 1) * ldc + m]     = h1;
                    Ch[(size_t)n * ldc + m + 8]       = h2;
                    Ch[(size_t)(n + 1) * ldc + m + 8] = h3;
                }
            }
        }
    }

    // ---------------- fused column softmax partials (EPI 3) ----------------
    if (EPI == 3) {
        __syncthreads();
        float* st = (float*)smem;

        float cm[8], cz[8];
#pragma unroll
        for (int nf = 0; nf < 4; nf++) {
#pragma unroll
            for (int e = 0; e < 2; e++) {
                float mx = NEG_INF;
#pragma unroll
                for (int mf = 0; mf < 4; mf++) {
                    mx = fmaxf(mx, acc[mf][nf][e]);
                    mx = fmaxf(mx, acc[mf][nf][e + 2]);
                }
                float zz = 0.f;
#pragma unroll
                for (int mf = 0; mf < 4; mf++)
                    zz += fast_exp(acc[mf][nf][e] - mx) + fast_exp(acc[mf][nf][e + 2] - mx);
                cm[nf * 2 + e] = mx;
                cz[nf * 2 + e] = zz;
            }
        }
#pragma unroll
        for (int off = 4; off < 32; off <<= 1) {
#pragma unroll
            for (int c = 0; c < 8; c++) {
                const float om = __shfl_xor_sync(0xffffffff, cm[c], off);
                const float oz = __shfl_xor_sync(0xffffffff, cz[c], off);
                const float mn = fmaxf(cm[c], om);
                cz[c] = cz[c] * fast_exp(cm[c] - mn) + oz * fast_exp(om - mn);
                cm[c] = mn;
            }
        }
        if ((lid >> 2) == 0) {
#pragma unroll
            for (int nf = 0; nf < 4; nf++)
#pragma unroll
                for (int e = 0; e < 2; e++) {
                    const int col = wn * 32 + nf * 8 + (lid & 3) * 2 + e;
                    st[(wm * 128 + col) * 2 + 0] = cm[nf * 2 + e];
                    st[(wm * 128 + col) * 2 + 1] = cz[nf * 2 + e];
                }
        }
        __syncthreads();
        if (tid < 128) {
            const float m0v = st[tid * 2],         z0v = st[tid * 2 + 1];
            const float m1v = st[(128 + tid) * 2], z1v = st[(128 + tid) * 2 + 1];
            const float mn = fmaxf(m0v, m1v);
            const float zz = z0v * fast_exp(m0v - mn) + z1v * fast_exp(m1v - mn);
            const size_t o = ((size_t)blockIdx.y * BATCH + blockIdx.z) * SEQ + n0 + tid;
            g_cm[o] = mn;
            g_cz[o] = zz;
        }
    }
}

// ============================ PV GEMM (fused exp) ============================
// O[m,n] = sum_k exp(S[m,k] - c_k) * Vh[n,k]   -- single MMA per k-step
#define PV_STG 16384   // A 8KB + B 8KB per stage

__global__ void __launch_bounds__(TCT, 2)
pv_gemm(const float* __restrict__ S, const __half* __restrict__ Vh,
        const float* __restrict__ Cv, float* __restrict__ O)
{
    extern __shared__ __align__(128) char smem[];
    const uint32_t sb = smem_u32(smem);

    const int tid = threadIdx.x;
    const int lid = tid & 31;
    const int wid = tid >> 5;
    const int wm  = wid >> 2;
    const int wn  = wid & 3;

    const long z = blockIdx.z;
    S  += z * (long)SEQ * SEQ;
    Cv += z * SEQ;
    O  += z * (long)SEQ * DIM;

    const int m0 = blockIdx.y * 128;
    const int n0 = blockIdx.x * 128;
    const int nstage = SEQ / 32;       // 128

    // per-thread A chunk coords (2 chunks of 16B-fp16 = 8 elems each)
    int cr[2], cc[2];
    uint32_t cdoff[2];
#pragma unroll
    for (int i = 0; i < 2; i++) {
        const int chunk = i * 256 + tid;
        cr[i] = chunk >> 2;
        cc[i] = chunk & 3;
        cdoff[i] = cr[i] * 64 + ((cc[i] ^ ((cr[i] + (cr[i] >> 2)) & 3)) * 16);
    }

    auto issueB = [&](int s) {
        const uint32_t base = sb + (s & 1) * PV_STG + 8192;
        const int k0 = s * 32;
#pragma unroll
        for (int i = 0; i < 2; i++)
            cp16(base + cdoff[i],
                 Vh + (size_t)(n0 + cr[i]) * MTOT + z * SEQ + k0 + cc[i] * 8);
        cp_commit();
    };

    float4 ra[2][2][2];   // [slot][chunk][half]
    float4 rc[2][2][2];
    auto loadA = [&](int s, int slot) {
#pragma unroll
        for (int i = 0; i < 2; i++) {
            const float* ap = S + (size_t)(m0 + cr[i]) * SEQ + s * 32 + cc[i] * 8;
            ra[slot][i][0] = *(const float4*)ap;
            ra[slot][i][1] = *(const float4*)(ap + 4);
            const float* cp2 = Cv + s * 32 + cc[i] * 8;
            rc[slot][i][0] = *(const float4*)cp2;
            rc[slot][i][1] = *(const float4*)(cp2 + 4);
        }
    };
    auto stsA = [&](int s, int slot) {
        const uint32_t base = (s & 1) * PV_STG;
#pragma unroll
        for (int i = 0; i < 2; i++) {
            __half h[8];
#pragma unroll
            for (int e = 0; e < 2; e++) {
                const float* a = (const float*)&ra[slot][i][e];
                const float* c = (const float*)&rc[slot][i][e];
#pragma unroll
                for (int j = 0; j < 4; j++)
                    h[e * 4 + j] = __float2half_rn(fast_exp(a[j] - c[j]));
            }
            *(uint4*)(smem + base + cdoff[i]) = *(const uint4*)h;
        }
    };

    float acc[4][4][4];
#pragma unroll
    for (int a = 0; a < 4; a++)
#pragma unroll
        for (int b = 0; b < 4; b++)
#pragma unroll
            for (int c = 0; c < 4; c++) acc[a][b][c] = 0.f;

    const int sub   = lid >> 3;
    const int lane7 = lid & 7;
    const int rA = wm * 64 + (sub & 1) * 8 + lane7;
    const int rB = wn * 32 + (sub & 1) * 8 + lane7;
    const int cs = sub >> 1;
    const int swA = (rA + (rA >> 2)) & 3;
    const int swB = (rB + (rB >> 2)) & 3;

    loadA(0, 0); issueB(0);
    loadA(1, 1); issueB(1);

    for (int s = 0; s < nstage; s++) {
        if (s + 1 < nstage) cp_wait<1>(); else cp_wait<0>();
        __syncthreads();                 // ldsm of s-1 complete -> bufs reusable

        stsA(s, s & 1);
        if (s + 2 < nstage) loadA(s + 2, s & 1);   // LDG in flight behind MMAs
        __syncthreads();                 // A(s) visible

        const uint32_t stg = sb + (s & 1) * PV_STG;
#pragma unroll
        for (int kt = 0; kt < 2; kt++) {
            const int ch = 2 * kt + cs;
            uint32_t aH[4][4], bH[2][4];
#pragma unroll
            for (int mf = 0; mf < 4; mf++)
                ldsm4(aH[mf], stg + (rA + mf * 16) * 64 + ((ch ^ swA) * 16));
#pragma unroll
            for (int bg = 0; bg < 2; bg++)
                ldsm4(bH[bg], stg + 8192 + (rB + bg * 16) * 64 + ((ch ^ swB) * 16));
#pragma unroll
            for (int mf = 0; mf < 4; mf++)
#pragma unroll
                for (int nf = 0; nf < 4; nf++)
                    mma16816(acc[mf][nf], aH[mf],
                             bH[nf >> 1][nf & 1], bH[nf >> 1][(nf & 1) + 2]);
        }

        if (s + 2 < nstage) {
            __syncthreads();             // B(s) reads done -> refill buffer
            issueB(s + 2);
        }
    }

#pragma unroll
    for (int mf = 0; mf < 4; mf++)
#pragma unroll
        for (int nf = 0; nf < 4; nf++) {
            const int m = m0 + wm * 64 + mf * 16 + (lid >> 2);
            const int n = n0 + wn * 32 + nf * 8 + (lid & 3) * 2;
            *(float2*)(O + (size_t)m * DIM + n) =
                make_float2(acc[mf][nf][0], acc[mf][nf][1]);
            *(float2*)(O + (size_t)(m + 8) * DIM + n) =
                make_float2(acc[mf][nf][2], acc[mf][nf][3]);
        }
}

// ---------------------------------------------------------------------------
__global__ void __launch_bounds__(256)
split_hl(const float* __restrict__ src, __half* __restrict__ h,
         __half* __restrict__ l, int n4)
{
    const int i = blockIdx.x * 256 + threadIdx.x;
    if (i >= n4) return;
    const float4 v = ((const float4*)src)[i];
    float vv[4] = {v.x, v.y, v.z, v.w};
    __half hh[4], ll[4];
#pragma unroll
    for (int e = 0; e < 4; e++) {
        hh[e] = __float2half_rn(vv[e]);
        ll[e] = __float2half_rn(vv[e] - __half2float(hh[e]));
    }
    ((__half2*)h)[i * 2]     = __halves2half2(hh[0], hh[1]);
    ((__half2*)h)[i * 2 + 1] = __halves2half2(hh[2], hh[3]);
    ((__half2*)l)[i * 2]     = __halves2half2(ll[0], ll[1]);
    ((__half2*)l)[i * 2 + 1] = __halves2half2(ll[2], ll[3]);
}

// ---------------------------------------------------------------------------
// merge per-qtile partial (m,z) -> c = m + ln(z)
__global__ void __launch_bounds__(256)
combine_stats()
{
    const int i = blockIdx.x * 256 + threadIdx.x;   // over BATCH*SEQ
    float m = NEG_INF;
#pragma unroll 4
    for (int t = 0; t < NTILE; t++)
        m = fmaxf(m, g_cm[(size_t)t * BATCH * SEQ + i]);
    float zz = 0.f;
#pragma unroll 4
    for (int t = 0; t < NTILE; t++) {
        const size_t o = (size_t)t * BATCH * SEQ + i;
        zz += g_cz[o] * fast_exp(g_cm[o] - m);
    }
    g_c[i] = m + logf(zz);
}

// ---------------------------------------------------------------------------
extern "C" void kernel_launch(void* const* d_in, const int* in_sizes, int n_in,
                              void* d_out, int out_size)
{
    const float* X  = (const float*)d_in[0];
    const float* Wq = (const float*)d_in[1];
    const float* bq = (const float*)d_in[2];
    const float* Wk = (const float*)d_in[3];
    const float* bk = (const float*)d_in[4];
    const float* Wv = (const float*)d_in[5];
    const float* bv = (const float*)d_in[6];
    float* out = (float*)d_out;

    __half *pXh, *pXl, *pWh, *pWl, *pQh, *pQl, *pKh, *pKl, *pVth;
    float  *pS, *pC;
    cudaGetSymbolAddress((void**)&pXh,  g_Xh);
    cudaGetSymbolAddress((void**)&pXl,  g_Xl);
    cudaGetSymbolAddress((void**)&pWh,  g_Wh);
    cudaGetSymbolAddress((void**)&pWl,  g_Wl);
    cudaGetSymbolAddress((void**)&pQh,  g_Qh);
    cudaGetSymbolAddress((void**)&pQl,  g_Ql);
    cudaGetSymbolAddress((void**)&pKh,  g_Kh);
    cudaGetSymbolAddress((void**)&pKl,  g_Kl);
    cudaGetSymbolAddress((void**)&pVth, g_Vth);
    cudaGetSymbolAddress((void**)&pS,   g_S);
    cudaGetSymbolAddress((void**)&pC,   g_c);

    cudaFuncSetAttribute(gemm_hl<1>, cudaFuncAttributeMaxDynamicSharedMemorySize, 65536);
    cudaFuncSetAttribute(gemm_hl<2>, cudaFuncAttributeMaxDynamicSharedMemorySize, 65536);
    cudaFuncSetAttribute(gemm_hl<3>, cudaFuncAttributeMaxDynamicSharedMemorySize, 65536);
    cudaFuncSetAttribute(pv_gemm,    cudaFuncAttributeMaxDynamicSharedMemorySize, 32768);

    const dim3 blk(TCT);

    // split inputs into fp16 hi/lo planes
    split_hl<<<(MTOT * DIM / 4 + 255) / 256, 256>>>(X,  pXh, pXl, MTOT * DIM / 4);
    split_hl<<<(DIM * DIM / 4 + 255) / 256, 256>>>(Wq, pWh,                 pWl,                 DIM * DIM / 4);
    split_hl<<<(DIM * DIM / 4 + 255) / 256, 256>>>(Wk, pWh + DIM * DIM,     pWl + DIM * DIM,     DIM * DIM / 4);
    split_hl<<<(DIM * DIM / 4 + 255) / 256, 256>>>(Wv, pWh + 2 * DIM * DIM, pWl + 2 * DIM * DIM, DIM * DIM / 4);

    // QKV projections (K=512)
    const dim3 gQKV(DIM / 128, MTOT / 128, 1);
    gemm_hl<1><<<gQKV, blk, 65536>>>(pXh, pXl, pWh,                 pWl,                 bq,
                                     nullptr, pQh, pQl, DIM, DIM, DIM, DIM, 0, 0, 0);
    gemm_hl<1><<<gQKV, blk, 65536>>>(pXh, pXl, pWh + DIM * DIM,     pWl + DIM * DIM,     bk,
                                     nullptr, pKh, pKl, DIM, DIM, DIM, DIM, 0, 0, 0);
    gemm_hl<2><<<gQKV, blk, 65536>>>(pXh, pXl, pWh + 2 * DIM * DIM, pWl + 2 * DIM * DIM, bv,
                                     nullptr, pVth, nullptr, DIM, DIM, DIM, MTOT, 0, 0, 0);

    // S = Q K^T per batch (K=512), fp32 out + fused column stats partials
    const dim3 gS(SEQ / 128, SEQ / 128, BATCH);
    gemm_hl<3><<<gS, blk, 65536>>>(pQh, pQl, pKh, pKl, nullptr,
                                   pS, nullptr, nullptr, DIM, DIM, DIM, SEQ,
                                   (long)SEQ * DIM, (long)SEQ * DIM, (long)SEQ * SEQ);

    // merge partial stats -> c = m + lnZ
    combine_stats<<<(BATCH * SEQ) / 256, 256>>>();

    // O = exp(S - c) * V per batch (K=4096), single MMA, fused exp
    const dim3 gPV(DIM / 128, SEQ / 128, BATCH);
    pv_gemm<<<gPV, blk, 32768>>>(pS, pVth, pC, out);
}

// round 8
// speedup vs baseline: 1.2438x; 1.2438x over previous
#include <cuda_runtime.h>
#include <cuda_fp16.h>
#include <math.h>
#include <stdint.h>

#define BATCH 4
#define SEQ   4096
#define DIM   512
#define MTOT  (BATCH * SEQ)
#define NTILE (SEQ / 128)
#define NEG_INF __int_as_float(0xff800000)

// ---------------- scratch (static device globals; no allocation) ------------
__device__ __half g_Xh[(size_t)MTOT * DIM],  g_Xl[(size_t)MTOT * DIM];
__device__ __half g_Wh[3][DIM * DIM],        g_Wl[3][DIM * DIM];
__device__ __half g_Qh[(size_t)MTOT * DIM],  g_Ql[(size_t)MTOT * DIM];
__device__ __half g_Kh[(size_t)MTOT * DIM],  g_Kl[(size_t)MTOT * DIM];
__device__ __half g_Vth[(size_t)DIM * MTOT];               // V^T hi plane only
__device__ float  g_S [(size_t)BATCH * SEQ * SEQ];
__device__ __half g_Ph[(size_t)BATCH * SEQ * SEQ];
__device__ float  g_cm[(size_t)NTILE * BATCH * SEQ];
__device__ float  g_cz[(size_t)NTILE * BATCH * SEQ];
__device__ float  g_m [(size_t)BATCH * SEQ];
__device__ float  g_rz[(size_t)BATCH * SEQ];

// ---------------- fast exp on the FMA pipe -----------------------------------
__device__ __forceinline__ float fast_exp(float x) {
    x = fmaxf(x, -80.0f);
    const float y  = x * 1.4426950408889634f;
    const float t  = y + 12582912.0f;
    const int   ni = __float_as_int(t) - 0x4B400000;
    const float f  = y - (t - 12582912.0f);
    float p = 1.3333558146e-3f;
    p = fmaf(p, f, 9.6181291076e-3f);
    p = fmaf(p, f, 5.5504108664e-2f);
    p = fmaf(p, f, 2.4022650696e-1f);
    p = fmaf(p, f, 6.9314718056e-1f);
    p = fmaf(p, f, 1.0f);
    return __int_as_float(__float_as_int(p) + (ni << 23));
}

// ============================ PTX helpers ===================================
__device__ __forceinline__ uint32_t smem_u32(const void* p) {
    uint32_t a;
    asm("{ .reg .u64 t; cvta.to.shared.u64 t, %1; cvt.u32.u64 %0, t; }"
        : "=r"(a) : "l"(p));
    return a;
}
template<int N> __device__ __forceinline__ void cp_wait() {
    asm volatile("cp.async.wait_group %0;" :: "n"(N) : "memory");
}
__device__ __forceinline__ void cp_commit() {
    asm volatile("cp.async.commit_group;" ::: "memory");
}
__device__ __forceinline__ void cp16(uint32_t dst, const void* src) {
    asm volatile("cp.async.cg.shared.global [%0], [%1], 16;"
                 :: "r"(dst), "l"(src) : "memory");
}
__device__ __forceinline__ void ldsm4(uint32_t* r, uint32_t a) {
    asm volatile("ldmatrix.sync.aligned.m8n8.x4.shared.b16 {%0,%1,%2,%3}, [%4];"
                 : "=r"(r[0]), "=r"(r[1]), "=r"(r[2]), "=r"(r[3]) : "r"(a));
}
__device__ __forceinline__ void mma16816(float* d, const uint32_t* a,
                                         uint32_t b0, uint32_t b1) {
    asm volatile("mma.sync.aligned.m16n8k16.row.col.f32.f16.f16.f32 "
                 "{%0,%1,%2,%3},{%4,%5,%6,%7},{%8,%9},{%0,%1,%2,%3};"
                 : "+f"(d[0]), "+f"(d[1]), "+f"(d[2]), "+f"(d[3])
                 : "r"(a[0]), "r"(a[1]), "r"(a[2]), "r"(a[3]), "r"(b0), "r"(b1));
}

// ============================ GEMM (hi/lo fp16) ==============================
// C[m,n] = sum_k A[m,k]*B[n,k]
// ALO/BLO: whether A/B lo planes exist. MMAs: AhBh [+AlBh if ALO] [+AhBl if BLO]
// EPI 0: fp32 C[m][n], no bias
// EPI 1: fp16 hi/lo planes Ch/Cl[m][n] (+bias)
// EPI 2: fp16 hi plane Ch[n][m] (+bias)  -- transposed (for V^T)
// EPI 3: fp32 C[m][n] + per-tile column softmax stats -> g_cm/g_cz
#define TCT 256

template<int EPI, int ALO, int BLO>
__global__ void __launch_bounds__(TCT, 2)
gemm_hl(const __half* __restrict__ Ah, const __half* __restrict__ Al,
        const __half* __restrict__ Bh, const __half* __restrict__ Bl,
        const float* __restrict__ bias,
        float* __restrict__ C, __half* __restrict__ Ch, __half* __restrict__ Cl,
        int K, int lda, int ldb, int ldc,
        long sA, long sB, long sC)
{
    constexpr int OFF_AL = 8192;
    constexpr int OFF_BH = ALO ? 16384 : 8192;
    constexpr int OFF_BL = OFF_BH + 8192;
    constexpr int STG    = 8192 * (2 + ALO + BLO);

    extern __shared__ __align__(128) char smem[];
    const uint32_t sb = smem_u32(smem);

    const int tid = threadIdx.x;
    const int lid = tid & 31;
    const int wid = tid >> 5;
    const int wm  = wid >> 2;
    const int wn  = wid & 3;

    const long z = blockIdx.z;
    Ah += z * sA; if (ALO) Al += z * sA;
    Bh += z * sB; if (BLO) Bl += z * sB;
    if (EPI == 0 || EPI == 3) C += z * sC; else { Ch += z * sC; if (EPI == 1) Cl += z * sC; }

    const int m0 = blockIdx.y * 128;
    const int n0 = blockIdx.x * 128;

    const int nstage = K / 32;

    auto issue = [&](int s) {
        const uint32_t base = sb + (s & 1) * STG;
        const int k0 = s * 32;
#pragma unroll
        for (int i = 0; i < 2; i++) {
            const int chunk = i * 256 + tid;
            const int r = chunk >> 2;
            const int c = chunk & 3;
            const uint32_t doff = r * 64 + ((c ^ ((r + (r >> 2)) & 3)) * 16);
            const size_t ga = (size_t)(m0 + r) * lda + k0 + c * 8;
            const size_t gb = (size_t)(n0 + r) * ldb + k0 + c * 8;
            cp16(base + doff, Ah + ga);
            if (ALO) cp16(base + OFF_AL + doff, Al + ga);
            cp16(base + OFF_BH + doff, Bh + gb);
            if (BLO) cp16(base + OFF_BL + doff, Bl + gb);
        }
        cp_commit();
    };

    float acc[4][4][4];
#pragma unroll
    for (int a = 0; a < 4; a++)
#pragma unroll
        for (int b = 0; b < 4; b++)
#pragma unroll
            for (int c = 0; c < 4; c++) acc[a][b][c] = 0.f;

    const int sub   = lid >> 3;
    const int lane7 = lid & 7;
    const int rA = wm * 64 + (sub & 1) * 8 + lane7;
    const int rB = wn * 32 + (sub & 1) * 8 + lane7;
    const int cs = sub >> 1;
    const int swA = (rA + (rA >> 2)) & 3;
    const int swB = (rB + (rB >> 2)) & 3;

    issue(0);
    issue(1);

    for (int s = 0; s < nstage; s++) {
        if (s + 1 < nstage) cp_wait<1>(); else cp_wait<0>();
        __syncthreads();

        const uint32_t stg = sb + (s & 1) * STG;
#pragma unroll
        for (int kt = 0; kt < 2; kt++) {
            const int ch = 2 * kt + cs;
            const uint32_t aoff = ((ch ^ swA) * 16);
            const uint32_t boff = ((ch ^ swB) * 16);

            uint32_t aH[4][4], bH[2][4];
#pragma unroll
            for (int mf = 0; mf < 4; mf++)
                ldsm4(aH[mf], stg + (rA + mf * 16) * 64 + aoff);
#pragma unroll
            for (int bg = 0; bg < 2; bg++)
                ldsm4(bH[bg], stg + OFF_BH + (rB + bg * 16) * 64 + boff);

            // hi * hi
#pragma unroll
            for (int mf = 0; mf < 4; mf++)
#pragma unroll
                for (int nf = 0; nf < 4; nf++)
                    mma16816(acc[mf][nf], aH[mf],
                             bH[nf >> 1][nf & 1], bH[nf >> 1][(nf & 1) + 2]);

            // lo * hi
            if (ALO) {
                uint32_t aL[4][4];
#pragma unroll
                for (int mf = 0; mf < 4; mf++)
                    ldsm4(aL[mf], stg + OFF_AL + (rA + mf * 16) * 64 + aoff);
#pragma unroll
                for (int mf = 0; mf < 4; mf++)
#pragma unroll
                    for (int nf = 0; nf < 4; nf++)
                        mma16816(acc[mf][nf], aL[mf],
                                 bH[nf >> 1][nf & 1], bH[nf >> 1][(nf & 1) + 2]);
            }

            // hi * lo
            if (BLO) {
                uint32_t bL[2][4];
#pragma unroll
                for (int bg = 0; bg < 2; bg++)
                    ldsm4(bL[bg], stg + OFF_BL + (rB + bg * 16) * 64 + boff);
#pragma unroll
                for (int mf = 0; mf < 4; mf++)
#pragma unroll
                    for (int nf = 0; nf < 4; nf++)
                        mma16816(acc[mf][nf], aH[mf],
                                 bL[nf >> 1][nf & 1], bL[nf >> 1][(nf & 1) + 2]);
            }
        }

        if (s + 2 < nstage) {
            __syncthreads();
            issue(s + 2);
        }
    }

    // -------------------------- epilogue ------------------------------------
#pragma unroll
    for (int mf = 0; mf < 4; mf++) {
#pragma unroll
        for (int nf = 0; nf < 4; nf++) {
            const int m = m0 + wm * 64 + mf * 16 + (lid >> 2);
            const int n = n0 + wn * 32 + nf * 8 + (lid & 3) * 2;
            float v0 = acc[mf][nf][0], v1 = acc[mf][nf][1];
            float v2 = acc[mf][nf][2], v3 = acc[mf][nf][3];
            if (EPI == 1 || EPI == 2) {
                const float b0 = bias[n], b1 = bias[n + 1];
                v0 += b0; v1 += b1; v2 += b0; v3 += b1;
            }
            if (EPI == 0 || EPI == 3) {
                *(float2*)(C + (size_t)m * ldc + n)       = make_float2(v0, v1);
                *(float2*)(C + (size_t)(m + 8) * ldc + n) = make_float2(v2, v3);
            } else {
                __half h0 = __float2half_rn(v0), h1 = __float2half_rn(v1);
                __half h2 = __float2half_rn(v2), h3 = __float2half_rn(v3);
                if (EPI == 1) {
                    __half l0 = __float2half_rn(v0 - __half2float(h0));
                    __half l1 = __float2half_rn(v1 - __half2float(h1));
                    __half l2 = __float2half_rn(v2 - __half2float(h2));
                    __half l3 = __float2half_rn(v3 - __half2float(h3));
                    *(__half2*)(Ch + (size_t)m * ldc + n)       = __halves2half2(h0, h1);
                    *(__half2*)(Ch + (size_t)(m + 8) * ldc + n) = __halves2half2(h2, h3);
                    *(__half2*)(Cl + (size_t)m * ldc + n)       = __halves2half2(l0, l1);
                    *(__half2*)(Cl + (size_t)(m + 8) * ldc + n) = __halves2half2(l2, l3);
                } else {
                    Ch[(size_t)n * ldc + m]           = h0;
                    Ch[(size_t)(n + 1) * ldc + m]     = h1;
                    Ch[(size_t)n * ldc + m + 8]       = h2;
                    Ch[(size_t)(n + 1) * ldc + m + 8] = h3;
                }
            }
        }
    }

    // ---------------- fused column softmax partials (EPI 3) ----------------
    if (EPI == 3) {
        __syncthreads();
        float* st = (float*)smem;

        float cm[8], cz[8];
#pragma unroll
        for (int nf = 0; nf < 4; nf++) {
#pragma unroll
            for (int e = 0; e < 2; e++) {
                float mx = NEG_INF;
#pragma unroll
                for (int mf = 0; mf < 4; mf++) {
                    mx = fmaxf(mx, acc[mf][nf][e]);
                    mx = fmaxf(mx, acc[mf][nf][e + 2]);
                }
                float zz = 0.f;
#pragma unroll
                for (int mf = 0; mf < 4; mf++)
                    zz += fast_exp(acc[mf][nf][e] - mx) + fast_exp(acc[mf][nf][e + 2] - mx);
                cm[nf * 2 + e] = mx;
                cz[nf * 2 + e] = zz;
            }
        }
#pragma unroll
        for (int off = 4; off < 32; off <<= 1) {
#pragma unroll
            for (int c = 0; c < 8; c++) {
                const float om = __shfl_xor_sync(0xffffffff, cm[c], off);
                const float oz = __shfl_xor_sync(0xffffffff, cz[c], off);
                const float mn = fmaxf(cm[c], om);
                cz[c] = cz[c] * fast_exp(cm[c] - mn) + oz * fast_exp(om - mn);
                cm[c] = mn;
            }
        }
        if ((lid >> 2) == 0) {
#pragma unroll
            for (int nf = 0; nf < 4; nf++)
#pragma unroll
                for (int e = 0; e < 2; e++) {
                    const int col = wn * 32 + nf * 8 + (lid & 3) * 2 + e;
                    st[(wm * 128 + col) * 2 + 0] = cm[nf * 2 + e];
                    st[(wm * 128 + col) * 2 + 1] = cz[nf * 2 + e];
                }
        }
        __syncthreads();
        if (tid < 128) {
            const float m0v = st[tid * 2],         z0v = st[tid * 2 + 1];
            const float m1v = st[(128 + tid) * 2], z1v = st[(128 + tid) * 2 + 1];
            const float mn = fmaxf(m0v, m1v);
            const float zz = z0v * fast_exp(m0v - mn) + z1v * fast_exp(m1v - mn);
            const size_t o = ((size_t)blockIdx.y * BATCH + blockIdx.z) * SEQ + n0 + tid;
            g_cm[o] = mn;
            g_cz[o] = zz;
        }
    }
}

// ---------------------------------------------------------------------------
__global__ void __launch_bounds__(256)
split_hl(const float* __restrict__ src, __half* __restrict__ h,
         __half* __restrict__ l, int n4)
{
    const int i = blockIdx.x * 256 + threadIdx.x;
    if (i >= n4) return;
    const float4 v = ((const float4*)src)[i];
    float vv[4] = {v.x, v.y, v.z, v.w};
    __half hh[4], ll[4];
#pragma unroll
    for (int e = 0; e < 4; e++) {
        hh[e] = __float2half_rn(vv[e]);
        ll[e] = __float2half_rn(vv[e] - __half2float(hh[e]));
    }
    ((__half2*)h)[i * 2]     = __halves2half2(hh[0], hh[1]);
    ((__half2*)h)[i * 2 + 1] = __halves2half2(hh[2], hh[3]);
    ((__half2*)l)[i * 2]     = __halves2half2(ll[0], ll[1]);
    ((__half2*)l)[i * 2 + 1] = __halves2half2(ll[2], ll[3]);
}

// ---------------------------------------------------------------------------
__global__ void __launch_bounds__(256)
combine_stats()
{
    const int i = blockIdx.x * 256 + threadIdx.x;
    float m = NEG_INF;
#pragma unroll 4
    for (int t = 0; t < NTILE; t++)
        m = fmaxf(m, g_cm[(size_t)t * BATCH * SEQ + i]);
    float zz = 0.f;
#pragma unroll 4
    for (int t = 0; t < NTILE; t++) {
        const size_t o = (size_t)t * BATCH * SEQ + i;
        zz += g_cz[o] * fast_exp(g_cm[o] - m);
    }
    g_m[i]  = m;
    g_rz[i] = 1.0f / zz;
}

// ---------------------------------------------------------------------------
// P = exp(S - m_k) * rz_k  -> single fp16 plane
__global__ void __launch_bounds__(256)
ppass()
{
    const int b = blockIdx.z;
    const size_t idx = ((size_t)blockIdx.x * 256 + threadIdx.x) * 4;
    const int k = (int)(idx & (SEQ - 1));

    const float4 s4 = *(const float4*)(g_S + (size_t)b * SEQ * SEQ + idx);
    const float4 m4 = *(const float4*)(g_m  + (size_t)b * SEQ + k);
    const float4 r4 = *(const float4*)(g_rz + (size_t)b * SEQ + k);

    __half h0 = __float2half_rn(fast_exp(s4.x - m4.x) * r4.x);
    __half h1 = __float2half_rn(fast_exp(s4.y - m4.y) * r4.y);
    __half h2 = __float2half_rn(fast_exp(s4.z - m4.z) * r4.z);
    __half h3 = __float2half_rn(fast_exp(s4.w - m4.w) * r4.w);

    const size_t o2 = ((size_t)b * SEQ * SEQ + idx) / 2;
    ((__half2*)g_Ph)[o2]     = __halves2half2(h0, h1);
    ((__half2*)g_Ph)[o2 + 1] = __halves2half2(h2, h3);
}

// ---------------------------------------------------------------------------
extern "C" void kernel_launch(void* const* d_in, const int* in_sizes, int n_in,
                              void* d_out, int out_size)
{
    const float* X  = (const float*)d_in[0];
    const float* Wq = (const float*)d_in[1];
    const float* bq = (const float*)d_in[2];
    const float* Wk = (const float*)d_in[3];
    const float* bk = (const float*)d_in[4];
    const float* Wv = (const float*)d_in[5];
    const float* bv = (const float*)d_in[6];
    float* out = (float*)d_out;

    __half *pXh, *pXl, *pWh, *pWl, *pQh, *pQl, *pKh, *pKl, *pVth, *pPh;
    float  *pS;
    cudaGetSymbolAddress((void**)&pXh,  g_Xh);
    cudaGetSymbolAddress((void**)&pXl,  g_Xl);
    cudaGetSymbolAddress((void**)&pWh,  g_Wh);
    cudaGetSymbolAddress((void**)&pWl,  g_Wl);
    cudaGetSymbolAddress((void**)&pQh,  g_Qh);
    cudaGetSymbolAddress((void**)&pQl,  g_Ql);
    cudaGetSymbolAddress((void**)&pKh,  g_Kh);
    cudaGetSymbolAddress((void**)&pKl,  g_Kl);
    cudaGetSymbolAddress((void**)&pVth, g_Vth);
    cudaGetSymbolAddress((void**)&pPh,  g_Ph);
    cudaGetSymbolAddress((void**)&pS,   g_S);

    cudaFuncSetAttribute((const void*)gemm_hl<1,1,1>, cudaFuncAttributeMaxDynamicSharedMemorySize, 65536);
    cudaFuncSetAttribute((const void*)gemm_hl<2,1,1>, cudaFuncAttributeMaxDynamicSharedMemorySize, 65536);
    cudaFuncSetAttribute((const void*)gemm_hl<3,1,1>, cudaFuncAttributeMaxDynamicSharedMemorySize, 65536);
    cudaFuncSetAttribute((const void*)gemm_hl<0,0,0>, cudaFuncAttributeMaxDynamicSharedMemorySize, 32768);

    const dim3 blk(TCT);

    // split inputs into fp16 hi/lo planes
    split_hl<<<(MTOT * DIM / 4 + 255) / 256, 256>>>(X,  pXh, pXl, MTOT * DIM / 4);
    split_hl<<<(DIM * DIM / 4 + 255) / 256, 256>>>(Wq, pWh,                 pWl,                 DIM * DIM / 4);
    split_hl<<<(DIM * DIM / 4 + 255) / 256, 256>>>(Wk, pWh + DIM * DIM,     pWl + DIM * DIM,     DIM * DIM / 4);
    split_hl<<<(DIM * DIM / 4 + 255) / 256, 256>>>(Wv, pWh + 2 * DIM * DIM, pWl + 2 * DIM * DIM, DIM * DIM / 4);

    // QKV projections (K=512)
    const dim3 gQKV(DIM / 128, MTOT / 128, 1);
    gemm_hl<1,1,1><<<gQKV, blk, 65536>>>(pXh, pXl, pWh,                 pWl,                 bq,
                                         nullptr, pQh, pQl, DIM, DIM, DIM, DIM, 0, 0, 0);
    gemm_hl<1,1,1><<<gQKV, blk, 65536>>>(pXh, pXl, pWh + DIM * DIM,     pWl + DIM * DIM,     bk,
                                         nullptr, pKh, pKl, DIM, DIM, DIM, DIM, 0, 0, 0);
    gemm_hl<2,1,1><<<gQKV, blk, 65536>>>(pXh, pXl, pWh + 2 * DIM * DIM, pWl + 2 * DIM * DIM, bv,
                                         nullptr, pVth, nullptr, DIM, DIM, DIM, MTOT, 0, 0, 0);

    // S = Q K^T per batch (K=512), fp32 out + fused column stats partials
    const dim3 gS(SEQ / 128, SEQ / 128, BATCH);
    gemm_hl<3,1,1><<<gS, blk, 65536>>>(pQh, pQl, pKh, pKl, nullptr,
                                       pS, nullptr, nullptr, DIM, DIM, DIM, SEQ,
                                       (long)SEQ * DIM, (long)SEQ * DIM, (long)SEQ * SEQ);

    // merge partial stats
    combine_stats<<<(BATCH * SEQ) / 256, 256>>>();

    // P = exp(S - m) * rz -> single fp16 plane
    ppass<<<dim3((SEQ * SEQ) / (256 * 4), 1, BATCH), blk>>>();

    // O = P V per batch (K=4096), single-MMA path, fp32 out
    const dim3 gPV(DIM / 128, SEQ / 128, BATCH);
    gemm_hl<0,0,0><<<gPV, blk, 32768>>>(pPh, nullptr, pVth, nullptr, nullptr,
                                        out, nullptr, nullptr, SEQ, SEQ, MTOT, DIM,
                                        (long)SEQ * SEQ, SEQ, (long)SEQ * DIM);
}